// round 1
// baseline (speedup 1.0000x reference)
#include <cuda_runtime.h>
#include <cstdint>

// Problem constants (from reference setup_inputs)
#define B_     2
#define R_     512
#define C_     256
#define H0_    256   // feat0 H=W
#define H1_    128   // feat1 H=W
#define POOL_  7
#define NBOX_  (B_ * R_)            // 1024
#define NCELL_ (NBOX_ * POOL_ * POOL_)  // 50176
#define CG_    (C_ / 4)             // 64 float4 groups per pixel

__global__ __launch_bounds__(CG_) void roialign_kernel(
    const float* __restrict__ feat0,
    const float* __restrict__ feat1,
    const float* __restrict__ rois,
    float* __restrict__ out)
{
    int cell = blockIdx.x;            // n*49 + py*7 + px
    int n    = cell / 49;
    int pc   = cell - n * 49;
    int py   = pc / 7;
    int px   = pc - py * 7;
    int b    = n >> 9;                // n / R_

    const float* roi = rois + (size_t)n * 5;
    float y1 = roi[0], x1 = roi[1], y2 = roi[2], x2 = roi[3];

    // level select: (h > 48) | (w > 48)  -> feat1 (coarse), else feat0
    bool lvl = ((y2 - y1) > 48.0f) || ((x2 - x1) > 48.0f);
    const float* feat = lvl ? feat1 : feat0;
    int   H    = lvl ? H1_ : H0_;     // W == H for both levels
    float Hm1  = (float)(H - 1);

    // normalized boxes (exact: /1024 is power of two)
    const float inv = 1.0f / 1024.0f;
    float y1n = y1 * inv, x1n = x1 * inv, y2n = y2 * inv, x2n = x2 * inv;

    float ry = (float)py / 6.0f;
    float rx = (float)px / 6.0f;
    float ys = (y1n + ry * (y2n - y1n)) * Hm1;
    float xs = (x1n + rx * (x2n - x1n)) * Hm1;

    float4* outp = (float4*)(out + (size_t)cell * C_);
    int t = threadIdx.x;

    bool valid = (ys >= 0.0f) && (ys <= Hm1) && (xs >= 0.0f) && (xs <= Hm1);
    if (!valid) {
        outp[t] = make_float4(0.f, 0.f, 0.f, 0.f);
        return;
    }

    float y0f = floorf(ys);
    float x0f = floorf(xs);
    float wy  = ys - y0f;
    float wx  = xs - x0f;
    int y0 = (int)y0f;            // valid => y0f in [0, H-1]
    int x0 = (int)x0f;
    int yp = min(y0 + 1, H - 1);
    int xp = min(x0 + 1, H - 1);

    size_t rowsz = (size_t)H * C_;            // W == H
    const float4* p00 = (const float4*)(feat + ((size_t)b * H + y0) * rowsz + (size_t)x0 * C_);
    const float4* p01 = (const float4*)(feat + ((size_t)b * H + y0) * rowsz + (size_t)xp * C_);
    const float4* p10 = (const float4*)(feat + ((size_t)b * H + yp) * rowsz + (size_t)x0 * C_);
    const float4* p11 = (const float4*)(feat + ((size_t)b * H + yp) * rowsz + (size_t)xp * C_);

    float4 a = __ldg(p00 + t);
    float4 c = __ldg(p01 + t);
    float4 d = __ldg(p10 + t);
    float4 e = __ldg(p11 + t);

    float omwx = 1.0f - wx;
    float omwy = 1.0f - wy;

    float4 r;
    r.x = (a.x * omwx + c.x * wx) * omwy + (d.x * omwx + e.x * wx) * wy;
    r.y = (a.y * omwx + c.y * wx) * omwy + (d.y * omwx + e.y * wx) * wy;
    r.z = (a.z * omwx + c.z * wx) * omwy + (d.z * omwx + e.z * wx) * wy;
    r.w = (a.w * omwx + c.w * wx) * omwy + (d.w * omwx + e.w * wx) * wy;

    outp[t] = r;
}

extern "C" void kernel_launch(void* const* d_in, const int* in_sizes, int n_in,
                              void* d_out, int out_size)
{
    const float* feat0 = (const float*)d_in[0];
    const float* feat1 = (const float*)d_in[1];
    const float* rois  = (const float*)d_in[2];
    float* out = (float*)d_out;

    roialign_kernel<<<NCELL_, CG_>>>(feat0, feat1, rois, out);
}

// round 2
// speedup vs baseline: 1.6453x; 1.6453x over previous
#include <cuda_runtime.h>
#include <cstdint>

// Problem constants (from reference setup_inputs)
#define B_     2
#define R_     512
#define C_     256
#define H0_    256   // feat0 H=W
#define H1_    128   // feat1 H=W
#define POOL_  7
#define NBOX_  (B_ * R_)            // 1024
#define NCELLB_ 49                  // cells per box
#define CG_    (C_ / 4)             // 64 float4 groups per pixel
#define THREADS_ 256                // 64 cgroups x 4 cell-lanes

struct CellDesc {
    int o00, o01, o10, o11;  // float4-unit offsets into selected feature map (-1 => invalid)
    float wx, wy;
};

__global__ __launch_bounds__(THREADS_) void roialign_kernel(
    const float* __restrict__ feat0,
    const float* __restrict__ feat1,
    const float* __restrict__ rois,
    float* __restrict__ out)
{
    __shared__ CellDesc cd[NCELLB_];
    __shared__ int s_lvl;

    int n = blockIdx.x;              // box index 0..1023
    int t = threadIdx.x;

    // ---- per-box setup: threads 0..48 build cell descriptors ----
    if (t < NCELLB_) {
        const float* roi = rois + (size_t)n * 5;
        float y1 = roi[0], x1 = roi[1], y2 = roi[2], x2 = roi[3];
        bool lvl = ((y2 - y1) > 48.0f) || ((x2 - x1) > 48.0f);
        if (t == 0) s_lvl = lvl ? 1 : 0;
        int H = lvl ? H1_ : H0_;
        float Hm1 = (float)(H - 1);
        int b = n >> 9;              // n / R_

        const float inv = 1.0f / 1024.0f;
        float y1n = y1 * inv, x1n = x1 * inv, y2n = y2 * inv, x2n = x2 * inv;

        int py = t / 7;
        int px = t - py * 7;
        float ry = (float)py * (1.0f / 6.0f);
        float rx = (float)px * (1.0f / 6.0f);
        float ys = (y1n + ry * (y2n - y1n)) * Hm1;
        float xs = (x1n + rx * (x2n - x1n)) * Hm1;

        CellDesc d;
        bool valid = (ys >= 0.0f) && (ys <= Hm1) && (xs >= 0.0f) && (xs <= Hm1);
        if (!valid) {
            d.o00 = -1; d.o01 = -1; d.o10 = -1; d.o11 = -1;
            d.wx = 0.0f; d.wy = 0.0f;
        } else {
            float y0f = floorf(ys);
            float x0f = floorf(xs);
            d.wy = ys - y0f;
            d.wx = xs - x0f;
            int y0 = (int)y0f;
            int x0 = (int)x0f;
            int yp = min(y0 + 1, H - 1);
            int xp = min(x0 + 1, H - 1);
            // offsets in float4 units: ((b*H + y)*H + x) * CG_
            int base_b = b * H;
            d.o00 = ((base_b + y0) * H + x0) * CG_;
            d.o01 = ((base_b + y0) * H + xp) * CG_;
            d.o10 = ((base_b + yp) * H + x0) * CG_;
            d.o11 = ((base_b + yp) * H + xp) * CG_;
        }
        cd[t] = d;
    }
    __syncthreads();

    const float4* feat = (const float4*)(s_lvl ? feat1 : feat0);
    int cg   = t & (CG_ - 1);        // channel group 0..63
    int lane = t >> 6;               // cell lane 0..3

    float4* outbase = (float4*)(out + (size_t)n * NCELLB_ * C_);

    #pragma unroll 4
    for (int cell = lane; cell < NCELLB_; cell += 4) {
        CellDesc d = cd[cell];
        float4* op = outbase + cell * CG_ + cg;
        if (d.o00 < 0) {
            __stcs(op, make_float4(0.f, 0.f, 0.f, 0.f));
            continue;
        }
        float4 a = __ldg(feat + d.o00 + cg);
        float4 c = __ldg(feat + d.o01 + cg);
        float4 e = __ldg(feat + d.o10 + cg);
        float4 f = __ldg(feat + d.o11 + cg);

        float wx = d.wx, wy = d.wy;
        float omwx = 1.0f - wx;
        float omwy = 1.0f - wy;

        float4 r;
        r.x = (a.x * omwx + c.x * wx) * omwy + (e.x * omwx + f.x * wx) * wy;
        r.y = (a.y * omwx + c.y * wx) * omwy + (e.y * omwx + f.y * wx) * wy;
        r.z = (a.z * omwx + c.z * wx) * omwy + (e.z * omwx + f.z * wx) * wy;
        r.w = (a.w * omwx + c.w * wx) * omwy + (e.w * omwx + f.w * wx) * wy;

        __stcs(op, r);
    }
}

extern "C" void kernel_launch(void* const* d_in, const int* in_sizes, int n_in,
                              void* d_out, int out_size)
{
    const float* feat0 = (const float*)d_in[0];
    const float* feat1 = (const float*)d_in[1];
    const float* rois  = (const float*)d_in[2];
    float* out = (float*)d_out;

    roialign_kernel<<<NBOX_, THREADS_>>>(feat0, feat1, rois, out);
}